// round 16
// baseline (speedup 1.0000x reference)
#include <cuda_runtime.h>
#include <cuda_fp16.h>
#include <stdint.h>
#include <math.h>

#define NB   32
#define DIM  1024
#define EPSF 1e-12f
#define SM_SCALE 128.0f
#define SM_DESCALE 0.0078125f

// ---------------- scratch (__device__ globals; no allocations) ----------------
__device__ __align__(128) __half g_Wk_h[DIM*DIM],  g_Wq_h[DIM*DIM];
__device__ __align__(128) __half g_X_h [NB*DIM*DIM];
__device__ __align__(128) __half g_XT_h[NB*DIM*DIM];
__device__ __align__(128) __half g_KT_h[NB*DIM*DIM];
__device__ __align__(128) __half g_QT_h[NB*DIM*DIM];
__device__ __align__(128) __half g_SM_h[NB*DIM*DIM];
__device__ __align__(128) float  g_YT[NB*DIM*DIM];
__device__ float g_partK[8*NB*DIM], g_partQ[8*NB*DIM];
__device__ float g_DK2[NB*DIM], g_DQ2[NB*DIM];

// ---------------- helpers ----------------
__device__ __forceinline__ uint32_t smem_to_u32(const void* p) {
    uint32_t a;
    asm("{ .reg .u64 t; cvta.to.shared.u64 t, %1; cvt.u32.u64 %0, t; }" : "=r"(a) : "l"(p));
    return a;
}

#define LDSM4(r, addr) \
    asm volatile("ldmatrix.sync.aligned.m8n8.x4.shared.b16 {%0,%1,%2,%3}, [%4];" \
        : "=r"((r)[0]), "=r"((r)[1]), "=r"((r)[2]), "=r"((r)[3]) : "r"(addr))

#define MMAF16(acc, a, b0, b1) \
    asm volatile("mma.sync.aligned.m16n8k16.row.col.f32.f16.f16.f32 " \
        "{%0,%1,%2,%3}, {%4,%5,%6,%7}, {%8,%9}, {%0,%1,%2,%3};" \
        : "+f"((acc)[0]), "+f"((acc)[1]), "+f"((acc)[2]), "+f"((acc)[3]) \
        : "r"((a)[0]), "r"((a)[1]), "r"((a)[2]), "r"((a)[3]), "r"(b0), "r"(b1))

// Stage (BK=64): A 16K + B 16K = 32 KB; fp16 tiles, full 128B rows, q = c^(r&7)
#define STAGE_BYTES 32768
#define NSTAGE 3
#define SMEM_BYTES (NSTAGE * STAGE_BYTES)   // 96 KB; epilogue fp32 [128][129]=66KB overlays

// ---------------------------------------------------------------------------
// Single-pass fp16 GEMM: D[m,n] = sum_k Ah[m,k]*Bh[n,k], K-major operands.
// CTA 128x128, 8 warps (2m x 4n), warp tile 64x32, BK=64, 3-stage cp.async,
// single barrier per chunk. A AND B fragments double-buffered (rolling across
// kk boundaries) so LDSM latency is never exposed mid-chunk. 2 CTAs/SM.
// EPI 0: fp16 TRANSPOSED store out[n][m], +bias, + exact deterministic
//        per-CTA partial column norms (from fp32 accumulators).
// EPI 1: fp32 TRANSPOSED store, * rsqrt(max(rs[m]*cs[n], eps))
// EPI 2: fp32 direct store out[m][n] * outScale
// ---------------------------------------------------------------------------
template <int EPI>
__global__ __launch_bounds__(256, 2)
void mma_gemm(const __half* __restrict__ Ah, size_t sA,
              const __half* __restrict__ Bh, size_t sB,
              float* __restrict__ outF, __half* __restrict__ oHi,
              const float* __restrict__ bias, const float* __restrict__ rs,
              const float* __restrict__ cs, float* __restrict__ partOut,
              float outScale)
{
    extern __shared__ char smem[];
    const int tid  = threadIdx.x;
    const int lane = tid & 31, warp = tid >> 5;
    const int wm = (warp >> 2) * 64, wn = (warp & 3) * 32;
    const int bz = blockIdx.z;
    const int bm = blockIdx.y * 128, bn = blockIdx.x * 128;
    const uint32_t sbase = smem_to_u32(smem);

    const __half* pAh = Ah + (size_t)bz * sA + (size_t)bm * DIM;
    const __half* pBh = Bh + (size_t)bz * sB + (size_t)bn * DIM;

    // tile: 128 rows x 128B (64 fp16); 16B chunk c (0..7) at q = c ^ (r&7)
    auto load_tile = [&](uint32_t dst, const __half* src, int kc) {
        #pragma unroll
        for (int j = 0; j < 4; j++) {
            int cid = tid + j * 256;           // 0..1023
            int r = cid >> 3, c = cid & 7;
            uint32_t q = (uint32_t)(c ^ (r & 7));
            asm volatile("cp.async.cg.shared.global [%0], [%1], 16;"
                         :: "r"(dst + (uint32_t)(r * 128) + q * 16),
                            "l"(src + (size_t)r * DIM + kc + c * 8));
        }
    };
    auto load_stage = [&](int s, int kc) {
        uint32_t St = sbase + (uint32_t)s * STAGE_BYTES;
        load_tile(St,          pAh, kc);
        load_tile(St + 16384,  pBh, kc);
        asm volatile("cp.async.commit_group;" ::: "memory");
    };

    // fragment address helpers (per-lane constant row/col components)
    const int rb_base = wn + ((lane >> 4) << 3) + (lane & 7);
    const int ra_base = wm + (lane & 15);
    auto b_addr = [&](uint32_t Bb, int kk, int g) {
        int r = rb_base + g * 16;
        uint32_t c = (uint32_t)(kk * 2 + ((lane >> 3) & 1));
        uint32_t q = c ^ (uint32_t)(r & 7);
        return Bb + (uint32_t)(r * 128) + q * 16;
    };
    auto a_addr = [&](uint32_t Ab, int kk, int im) {
        int r = ra_base + im * 16;
        uint32_t c = (uint32_t)(kk * 2 + (lane >> 4));
        uint32_t q = c ^ (uint32_t)(r & 7);
        return Ab + (uint32_t)(r * 128) + q * 16;
    };

    float acc[4][4][4];
    #pragma unroll
    for (int a = 0; a < 4; a++)
        #pragma unroll
        for (int b = 0; b < 4; b++)
            #pragma unroll
            for (int c = 0; c < 4; c++)
                acc[a][b][c] = 0.0f;

    load_stage(0, 0);
    load_stage(1, 64);

    const int NCHUNK = 16;   // K / 64
    for (int i = 0; i < NCHUNK; i++) {
        if (i + 1 < NCHUNK) {
            asm volatile("cp.async.wait_group 1;" ::: "memory");
        } else {
            asm volatile("cp.async.wait_group 0;" ::: "memory");
        }
        __syncthreads();   // stage i visible; all warps done with chunk i-1

        // issue next stage's loads FIRST (WAR-safe: stage (i+2)%3 readers
        // finished before this barrier) so LSU work overlaps this chunk
        if (i + 2 < NCHUNK)
            load_stage((i + 2) % NSTAGE, (i + 2) * 64);

        const uint32_t Ab = sbase + (uint32_t)(i % NSTAGE) * STAGE_BYTES;
        const uint32_t Bb = Ab + 16384;

        uint32_t bf[2][8], af[2][4];
        // prologue: B frags kk=0, A frag (kk=0, im=0)
        LDSM4(&bf[0][0], b_addr(Bb, 0, 0));
        LDSM4(&bf[0][4], b_addr(Bb, 0, 1));
        LDSM4(af[0],     a_addr(Ab, 0, 0));

        #pragma unroll
        for (int kk = 0; kk < 4; kk++) {
            const int bcur = kk & 1, bnxt = bcur ^ 1;
            if (kk < 3) {   // prefetch next kk's B fragments during MMAs
                LDSM4(&bf[bnxt][0], b_addr(Bb, kk + 1, 0));
                LDSM4(&bf[bnxt][4], b_addr(Bb, kk + 1, 1));
            }
            #pragma unroll
            for (int im = 0; im < 4; im++) {
                const int cur = im & 1, nxt = cur ^ 1;
                if (im < 3)
                    LDSM4(af[nxt], a_addr(Ab, kk, im + 1));
                else if (kk < 3)
                    LDSM4(af[nxt], a_addr(Ab, kk + 1, 0));
                #pragma unroll
                for (int jn = 0; jn < 4; jn++)
                    MMAF16(acc[im][jn], af[cur], bf[bcur][2 * jn], bf[bcur][2 * jn + 1]);
            }
        }
    }
    __syncthreads();

    // ---- epilogue: (+bias), stage through padded fp32 smem [128][129] ----
    float* sfl = (float*)smem;
    #pragma unroll
    for (int im = 0; im < 4; im++) {
        float bv0 = 0.f, bv1 = 0.f;
        if (EPI == 0) {
            bv0 = bias[bm + wm + im * 16 + (lane >> 2)];
            bv1 = bias[bm + wm + im * 16 + (lane >> 2) + 8];
        }
        #pragma unroll
        for (int jn = 0; jn < 4; jn++) {
            int m  = wm + im * 16 + (lane >> 2);
            int nn = wn + jn * 8 + 2 * (lane & 3);
            sfl[m * 129 + nn]           = acc[im][jn][0] + bv0;
            sfl[m * 129 + nn + 1]       = acc[im][jn][1] + bv0;
            sfl[(m + 8) * 129 + nn]     = acc[im][jn][2] + bv1;
            sfl[(m + 8) * 129 + nn + 1] = acc[im][jn][3] + bv1;
        }
    }
    __syncthreads();

    const size_t obase = (size_t)bz * (size_t)(DIM * DIM);
    if (EPI == 0) {
        #pragma unroll 1
        for (int idx = tid; idx < 128 * 128; idx += 256) {
            int nn = idx >> 7, m = idx & 127;
            float v = sfl[m * 129 + nn];
            oHi[obase + (size_t)(bn + nn) * DIM + bm + m] = __float2half(v);
        }
        // exact deterministic partial column norms over this CTA's 128 m rows
        float* sscr = (float*)(smem + 66304);     // [2][128]
        {
            int nn = tid & 127, mh = (tid >> 7) * 64;
            float ps = 0.0f;
            #pragma unroll 4
            for (int m = mh; m < mh + 64; m++) {
                float vv = sfl[m * 129 + nn];
                ps = fmaf(vv, vv, ps);
            }
            sscr[(tid >> 7) * 128 + nn] = ps;
        }
        __syncthreads();
        if (tid < 128)
            partOut[(size_t)(bm >> 7) * (NB * DIM) + (size_t)bz * DIM + bn + tid] =
                sscr[tid] + sscr[128 + tid];
    } else if (EPI == 1) {
        #pragma unroll 1
        for (int idx = tid; idx < 128 * 128; idx += 256) {
            int nn = idx >> 7, m = idx & 127;
            float v = sfl[m * 129 + nn];
            float sc = rsqrtf(fmaxf(rs[bz * DIM + bm + m] * cs[bz * DIM + bn + nn], EPSF));
            outF[obase + (size_t)(bn + nn) * DIM + bm + m] = v * sc;
        }
    } else {
        #pragma unroll 1
        for (int idx = tid; idx < 128 * 128; idx += 256) {
            int m = idx >> 7, nn = idx & 127;
            outF[obase + (size_t)(bm + m) * DIM + bn + nn] = sfl[m * 129 + nn] * outScale;
        }
    }
}

// ---------------------------------------------------------------------------
// Elementwise kernels
// ---------------------------------------------------------------------------
__global__ __launch_bounds__(256)
void w_split(const float* __restrict__ Wk, const float* __restrict__ Wq)
{
    int i = blockIdx.x * 256 + threadIdx.x;
    g_Wk_h[i] = __float2half(Wk[i]);
    g_Wq_h[i] = __float2half(Wq[i]);
}

// X[n][d][b] -> X_h (same layout) + XT_h [n][b][d]
__global__ __launch_bounds__(256)
void xprep(const float* __restrict__ X)
{
    __shared__ float t[32][33];
    const int n = blockIdx.z, b0 = blockIdx.x * 32, d0 = blockIdx.y * 32;
    const int tx = threadIdx.x, ty = threadIdx.y;
    const size_t base = (size_t)n << 20;
    const float* Xn = X + base;
    #pragma unroll
    for (int r = 0; r < 4; r++) {
        int row = ty + r * 8;
        float v = Xn[(size_t)(d0 + row) * DIM + b0 + tx];
        t[row][tx] = v;
        g_X_h[base + (size_t)(d0 + row) * DIM + b0 + tx] = __float2half(v);
    }
    __syncthreads();
    #pragma unroll
    for (int r = 0; r < 4; r++) {
        int row = ty + r * 8;
        g_XT_h[base + (size_t)(b0 + row) * DIM + d0 + tx] = __float2half(t[tx][row]);
    }
}

// Reduce 8 deterministic partials -> DK2/DQ2
__global__ __launch_bounds__(256)
void norms_red()
{
    int idx = blockIdx.x * 256 + threadIdx.x;
    float sk = 0.f, sq = 0.f;
    #pragma unroll
    for (int t = 0; t < 8; t++) {
        sk += g_partK[t * (NB * DIM) + idx];
        sq += g_partQ[t * (NB * DIM) + idx];
    }
    g_DK2[idx] = sk;
    g_DQ2[idx] = sq;
}

// Row softmax of YT -> SM (scaled x128) fp16
__global__ __launch_bounds__(256)
void softmax_k()
{
    const int row = blockIdx.x;
    const int tid = threadIdx.x;
    float* y = g_YT + ((size_t)row << 10);
    float v[4];
    #pragma unroll
    for (int j = 0; j < 4; j++) v[j] = y[tid + j * 256];
    float m = fmaxf(fmaxf(v[0], v[1]), fmaxf(v[2], v[3]));
    __shared__ float red[8];
    #pragma unroll
    for (int o = 16; o > 0; o >>= 1) m = fmaxf(m, __shfl_xor_sync(0xFFFFFFFFu, m, o));
    if ((tid & 31) == 0) red[tid >> 5] = m;
    __syncthreads();
    float mall = red[0];
    #pragma unroll
    for (int w = 1; w < 8; w++) mall = fmaxf(mall, red[w]);
    float s = 0.f;
    #pragma unroll
    for (int j = 0; j < 4; j++) { v[j] = __expf(v[j] - mall); s += v[j]; }
    #pragma unroll
    for (int o = 16; o > 0; o >>= 1) s += __shfl_xor_sync(0xFFFFFFFFu, s, o);
    __syncthreads();
    if ((tid & 31) == 0) red[tid >> 5] = s;
    __syncthreads();
    float st = 0.f;
    #pragma unroll
    for (int w = 0; w < 8; w++) st += red[w];
    const float inv = SM_SCALE / st;
    #pragma unroll
    for (int j = 0; j < 4; j++)
        g_SM_h[((size_t)row << 10) + tid + j * 256] = __float2half(v[j] * inv);
}

// ---------------------------------------------------------------------------
extern "C" void kernel_launch(void* const* d_in, const int* in_sizes, int n_in,
                              void* d_out, int out_size)
{
    const float* X   = (const float*)d_in[0];
    const float* Wk  = (const float*)d_in[1];
    const float* Wq  = (const float*)d_in[2];
    const float* Wk0 = (const float*)d_in[3];
    const float* Wq0 = (const float*)d_in[4];
    float* Z = (float*)d_out;

    cudaFuncSetAttribute(mma_gemm<0>, cudaFuncAttributeMaxDynamicSharedMemorySize, SMEM_BYTES);
    cudaFuncSetAttribute(mma_gemm<1>, cudaFuncAttributeMaxDynamicSharedMemorySize, SMEM_BYTES);
    cudaFuncSetAttribute(mma_gemm<2>, cudaFuncAttributeMaxDynamicSharedMemorySize, SMEM_BYTES);

    __half *Wkh, *Wqh, *Xh, *XTh, *KTh, *QTh, *SMh;
    float *YT, *dk2, *dq2, *pK, *pQ;
    cudaGetSymbolAddress((void**)&Wkh, g_Wk_h);   cudaGetSymbolAddress((void**)&Wqh, g_Wq_h);
    cudaGetSymbolAddress((void**)&Xh,  g_X_h);    cudaGetSymbolAddress((void**)&XTh, g_XT_h);
    cudaGetSymbolAddress((void**)&KTh, g_KT_h);   cudaGetSymbolAddress((void**)&QTh, g_QT_h);
    cudaGetSymbolAddress((void**)&SMh, g_SM_h);
    cudaGetSymbolAddress((void**)&YT,  g_YT);
    cudaGetSymbolAddress((void**)&dk2, g_DK2);    cudaGetSymbolAddress((void**)&dq2, g_DQ2);
    cudaGetSymbolAddress((void**)&pK,  g_partK);  cudaGetSymbolAddress((void**)&pQ,  g_partQ);

    const size_t S = (size_t)DIM * DIM;
    dim3 gg(8, 8, NB);

    w_split<<<(DIM * DIM) / 256, 256>>>(Wk, Wq);
    xprep<<<dim3(32, 32, NB), dim3(32, 8)>>>(X);

    // KT[b,c] = (Wk @ X)^T + Wk0 ; QT likewise; fused exact partial norms
    mma_gemm<0><<<gg, 256, SMEM_BYTES>>>(Wkh, 0, XTh, S,
                                         nullptr, KTh, Wk0, nullptr, nullptr, pK, 1.0f);
    mma_gemm<0><<<gg, 256, SMEM_BYTES>>>(Wqh, 0, XTh, S,
                                         nullptr, QTh, Wq0, nullptr, nullptr, pQ, 1.0f);
    norms_red<<<(NB * DIM) / 256, 256>>>();

    // YT[k,q] = (Q^T K)[q,k] * rsqrt(max(DQ2[q]*DK2[k], eps))
    mma_gemm<1><<<gg, 256, SMEM_BYTES>>>(QTh, S, KTh, S,
                                         YT, nullptr, nullptr, dq2, dk2, nullptr, 1.0f);
    softmax_k<<<NB * DIM, 256>>>();

    // Z = X @ (SM*128) / 128
    mma_gemm<2><<<gg, 256, SMEM_BYTES>>>(Xh, S, SMh, S,
                                         Z, nullptr, nullptr, nullptr, nullptr, nullptr,
                                         SM_DESCALE);
}

// round 17
// speedup vs baseline: 1.0879x; 1.0879x over previous
#include <cuda_runtime.h>
#include <cuda_fp16.h>
#include <stdint.h>
#include <math.h>

#define NB   32
#define DIM  1024
#define EPSF 1e-12f
#define SM_SCALE 128.0f
#define SM_DESCALE 0.0078125f

// ---------------- scratch (__device__ globals; no allocations) ----------------
__device__ __align__(128) __half g_Wk_h[DIM*DIM],  g_Wq_h[DIM*DIM];
__device__ __align__(128) __half g_X_h [NB*DIM*DIM];
__device__ __align__(128) __half g_XT_h[NB*DIM*DIM];
__device__ __align__(128) __half g_KT_h[NB*DIM*DIM];
__device__ __align__(128) __half g_QT_h[NB*DIM*DIM];
__device__ __align__(128) __half g_SM_h[NB*DIM*DIM];
__device__ __align__(128) float  g_YT[NB*DIM*DIM];
__device__ float g_partK[8*NB*DIM], g_partQ[8*NB*DIM];
__device__ float g_DK2[NB*DIM], g_DQ2[NB*DIM];

// ---------------- helpers ----------------
__device__ __forceinline__ uint32_t smem_to_u32(const void* p) {
    uint32_t a;
    asm("{ .reg .u64 t; cvta.to.shared.u64 t, %1; cvt.u32.u64 %0, t; }" : "=r"(a) : "l"(p));
    return a;
}

#define LDSM4(r, addr) \
    asm volatile("ldmatrix.sync.aligned.m8n8.x4.shared.b16 {%0,%1,%2,%3}, [%4];" \
        : "=r"((r)[0]), "=r"((r)[1]), "=r"((r)[2]), "=r"((r)[3]) : "r"(addr))

#define MMAF16(acc, a, b0, b1) \
    asm volatile("mma.sync.aligned.m16n8k16.row.col.f32.f16.f16.f32 " \
        "{%0,%1,%2,%3}, {%4,%5,%6,%7}, {%8,%9}, {%0,%1,%2,%3};" \
        : "+f"((acc)[0]), "+f"((acc)[1]), "+f"((acc)[2]), "+f"((acc)[3]) \
        : "r"((a)[0]), "r"((a)[1]), "r"((a)[2]), "r"((a)[3]), "r"(b0), "r"(b1))

// Stage (BK=64): A 16K + B 16K = 32 KB; fp16 tiles, full 128B rows, q = c^(r&7)
#define STAGE_BYTES 32768
#define NSTAGE 3
#define SMEM_BYTES (NSTAGE * STAGE_BYTES)   // 96 KB; EPI0 epilogue fp32 [128][129]=66KB overlays

// ---------------------------------------------------------------------------
// Single-pass fp16 GEMM: D[m,n] = sum_k Ah[m,k]*Bh[n,k], K-major operands.
// CTA 128x128, 8 warps (2m x 4n), warp tile 64x32, BK=64, 3-stage cp.async,
// single barrier per chunk. 2 CTAs/SM. Mainloop identical to the 838us R15.
// EPI 0: (merged K/Q: gridDim.z = 2*NB, z>=NB selects the second operand set)
//        fp16 TRANSPOSED store out[n][m], +bias, + exact deterministic
//        per-CTA partial column norms, via smem staging.
// EPI 1: fp32 TRANSPOSED store * rsqrt(max(rs[m]*cs[n], eps)) — DIRECT from
//        fragments (32B-sector aligned), no smem round trip.
// EPI 2: fp32 direct store out[m][n] * outScale — DIRECT float2 stores.
// ---------------------------------------------------------------------------
template <int EPI>
__global__ __launch_bounds__(256, 2)
void mma_gemm(const __half* __restrict__ Ah, const __half* __restrict__ Ah2, size_t sA,
              const __half* __restrict__ Bh, size_t sB,
              float* __restrict__ outF, __half* __restrict__ oHi, __half* __restrict__ oHi2,
              const float* __restrict__ bias, const float* __restrict__ bias2,
              const float* __restrict__ rs, const float* __restrict__ cs,
              float* __restrict__ partOut, float* __restrict__ partOut2,
              float outScale)
{
    extern __shared__ char smem[];
    const int tid  = threadIdx.x;
    const int lane = tid & 31, warp = tid >> 5;
    const int wm = (warp >> 2) * 64, wn = (warp & 3) * 32;
    int bz = blockIdx.z;
    const __half* Asel = Ah;
    const float*  biasSel = bias;
    __half*       oSel = oHi;
    float*        partSel = partOut;
    if (EPI == 0 && bz >= NB) {
        bz -= NB;
        Asel = Ah2; biasSel = bias2; oSel = oHi2; partSel = partOut2;
    }
    const int bm = blockIdx.y * 128, bn = blockIdx.x * 128;
    const uint32_t sbase = smem_to_u32(smem);

    const __half* pAh = Asel + (size_t)bz * sA + (size_t)bm * DIM;
    const __half* pBh = Bh + (size_t)bz * sB + (size_t)bn * DIM;

    // tile: 128 rows x 128B (64 fp16); 16B chunk c (0..7) at q = c ^ (r&7)
    auto load_tile = [&](uint32_t dst, const __half* src, int kc) {
        #pragma unroll
        for (int j = 0; j < 4; j++) {
            int cid = tid + j * 256;           // 0..1023
            int r = cid >> 3, c = cid & 7;
            uint32_t q = (uint32_t)(c ^ (r & 7));
            asm volatile("cp.async.cg.shared.global [%0], [%1], 16;"
                         :: "r"(dst + (uint32_t)(r * 128) + q * 16),
                            "l"(src + (size_t)r * DIM + kc + c * 8));
        }
    };
    auto load_stage = [&](int s, int kc) {
        uint32_t St = sbase + (uint32_t)s * STAGE_BYTES;
        load_tile(St,          pAh, kc);
        load_tile(St + 16384,  pBh, kc);
        asm volatile("cp.async.commit_group;" ::: "memory");
    };

    float acc[4][4][4];
    #pragma unroll
    for (int a = 0; a < 4; a++)
        #pragma unroll
        for (int b = 0; b < 4; b++)
            #pragma unroll
            for (int c = 0; c < 4; c++)
                acc[a][b][c] = 0.0f;

    load_stage(0, 0);
    load_stage(1, 64);

    const int NCHUNK = 16;   // K / 64
    for (int i = 0; i < NCHUNK; i++) {
        if (i + 1 < NCHUNK) {
            asm volatile("cp.async.wait_group 1;" ::: "memory");
        } else {
            asm volatile("cp.async.wait_group 0;" ::: "memory");
        }
        __syncthreads();   // stage i visible; all warps done with chunk i-1

        const uint32_t Ab = sbase + (uint32_t)(i % NSTAGE) * STAGE_BYTES;
        const uint32_t Bb = Ab + 16384;

        #pragma unroll
        for (int kk = 0; kk < 4; kk++) {
            uint32_t bh[8];
            {
                const int rb = wn + ((lane >> 4) << 3) + (lane & 7);
                const uint32_t c = (uint32_t)(kk * 2 + ((lane >> 3) & 1));
                #pragma unroll
                for (int g = 0; g < 2; g++) {
                    int r = rb + g * 16;
                    uint32_t q = c ^ (uint32_t)(r & 7);
                    LDSM4(&bh[g * 4], Bb + (uint32_t)(r * 128) + q * 16);
                }
            }
            const int ra = wm + (lane & 15);
            const uint32_t ca = (uint32_t)(kk * 2 + (lane >> 4));
            uint32_t af[2][4];
            {
                int r = ra;
                uint32_t q = ca ^ (uint32_t)(r & 7);
                LDSM4(af[0], Ab + (uint32_t)(r * 128) + q * 16);
            }
            #pragma unroll
            for (int im = 0; im < 4; im++) {
                const int cur = im & 1, nxt = cur ^ 1;
                if (im < 3) {
                    int r = ra + (im + 1) * 16;
                    uint32_t q = ca ^ (uint32_t)(r & 7);
                    LDSM4(af[nxt], Ab + (uint32_t)(r * 128) + q * 16);
                }
                #pragma unroll
                for (int jn = 0; jn < 4; jn++)
                    MMAF16(acc[im][jn], af[cur], bh[2 * jn], bh[2 * jn + 1]);
            }
        }

        // issue next loads AFTER compute (single-barrier pipeline, stage (i+2)%3)
        if (i + 2 < NCHUNK)
            load_stage((i + 2) % NSTAGE, (i + 2) * 64);
    }

    const size_t obase = (size_t)bz * (size_t)(DIM * DIM);

    if (EPI == 0) {
        __syncthreads();
        // ---- staged epilogue: +bias, fp32 smem [128][129], then fp16 store ----
        float* sfl = (float*)smem;
        #pragma unroll
        for (int im = 0; im < 4; im++) {
            float bv0 = biasSel[bm + wm + im * 16 + (lane >> 2)];
            float bv1 = biasSel[bm + wm + im * 16 + (lane >> 2) + 8];
            #pragma unroll
            for (int jn = 0; jn < 4; jn++) {
                int m  = wm + im * 16 + (lane >> 2);
                int nn = wn + jn * 8 + 2 * (lane & 3);
                sfl[m * 129 + nn]           = acc[im][jn][0] + bv0;
                sfl[m * 129 + nn + 1]       = acc[im][jn][1] + bv0;
                sfl[(m + 8) * 129 + nn]     = acc[im][jn][2] + bv1;
                sfl[(m + 8) * 129 + nn + 1] = acc[im][jn][3] + bv1;
            }
        }
        __syncthreads();
        #pragma unroll 1
        for (int idx = tid; idx < 128 * 128; idx += 256) {
            int nn = idx >> 7, m = idx & 127;
            float v = sfl[m * 129 + nn];
            oSel[obase + (size_t)(bn + nn) * DIM + bm + m] = __float2half(v);
        }
        // exact deterministic partial column norms over this CTA's 128 m rows
        float* sscr = (float*)(smem + 66304);     // [2][128]
        {
            int nn = tid & 127, mh = (tid >> 7) * 64;
            float ps = 0.0f;
            #pragma unroll 4
            for (int m = mh; m < mh + 64; m++) {
                float vv = sfl[m * 129 + nn];
                ps = fmaf(vv, vv, ps);
            }
            sscr[(tid >> 7) * 128 + nn] = ps;
        }
        __syncthreads();
        if (tid < 128)
            partSel[(size_t)(bm >> 7) * (NB * DIM) + (size_t)bz * DIM + bn + tid] =
                sscr[tid] + sscr[128 + tid];
    } else if (EPI == 1) {
        // ---- direct transposed store from fragments (32B-sector aligned) ----
        #pragma unroll
        for (int im = 0; im < 4; im++) {
            int m = wm + im * 16 + (lane >> 2);
            float r0 = rs[bz * DIM + bm + m];
            float r1 = rs[bz * DIM + bm + m + 8];
            #pragma unroll
            for (int jn = 0; jn < 4; jn++) {
                int nn = wn + jn * 8 + 2 * (lane & 3);
                float c0 = cs[bz * DIM + bn + nn];
                float c1 = cs[bz * DIM + bn + nn + 1];
                outF[obase + (size_t)(bn + nn)     * DIM + bm + m]     =
                    acc[im][jn][0] * rsqrtf(fmaxf(r0 * c0, EPSF));
                outF[obase + (size_t)(bn + nn + 1) * DIM + bm + m]     =
                    acc[im][jn][1] * rsqrtf(fmaxf(r0 * c1, EPSF));
                outF[obase + (size_t)(bn + nn)     * DIM + bm + m + 8] =
                    acc[im][jn][2] * rsqrtf(fmaxf(r1 * c0, EPSF));
                outF[obase + (size_t)(bn + nn + 1) * DIM + bm + m + 8] =
                    acc[im][jn][3] * rsqrtf(fmaxf(r1 * c1, EPSF));
            }
        }
    } else {
        // ---- direct row-major store from fragments (float2 = 8B stores) ----
        #pragma unroll
        for (int im = 0; im < 4; im++) {
            int m = wm + im * 16 + (lane >> 2);
            #pragma unroll
            for (int jn = 0; jn < 4; jn++) {
                int nn = wn + jn * 8 + 2 * (lane & 3);
                float2 p0 = make_float2(acc[im][jn][0] * outScale,
                                        acc[im][jn][1] * outScale);
                float2 p1 = make_float2(acc[im][jn][2] * outScale,
                                        acc[im][jn][3] * outScale);
                *(float2*)&outF[obase + (size_t)(bm + m)     * DIM + bn + nn] = p0;
                *(float2*)&outF[obase + (size_t)(bm + m + 8) * DIM + bn + nn] = p1;
            }
        }
    }
}

// ---------------------------------------------------------------------------
// Elementwise kernels
// ---------------------------------------------------------------------------
__global__ __launch_bounds__(256)
void w_split(const float* __restrict__ Wk, const float* __restrict__ Wq)
{
    int i = blockIdx.x * 256 + threadIdx.x;
    g_Wk_h[i] = __float2half(Wk[i]);
    g_Wq_h[i] = __float2half(Wq[i]);
}

// X[n][d][b] -> X_h (same layout) + XT_h [n][b][d]
__global__ __launch_bounds__(256)
void xprep(const float* __restrict__ X)
{
    __shared__ float t[32][33];
    const int n = blockIdx.z, b0 = blockIdx.x * 32, d0 = blockIdx.y * 32;
    const int tx = threadIdx.x, ty = threadIdx.y;
    const size_t base = (size_t)n << 20;
    const float* Xn = X + base;
    #pragma unroll
    for (int r = 0; r < 4; r++) {
        int row = ty + r * 8;
        float v = Xn[(size_t)(d0 + row) * DIM + b0 + tx];
        t[row][tx] = v;
        g_X_h[base + (size_t)(d0 + row) * DIM + b0 + tx] = __float2half(v);
    }
    __syncthreads();
    #pragma unroll
    for (int r = 0; r < 4; r++) {
        int row = ty + r * 8;
        g_XT_h[base + (size_t)(b0 + row) * DIM + d0 + tx] = __float2half(t[tx][row]);
    }
}

// Reduce 8 deterministic partials -> DK2/DQ2
__global__ __launch_bounds__(256)
void norms_red()
{
    int idx = blockIdx.x * 256 + threadIdx.x;
    float sk = 0.f, sq = 0.f;
    #pragma unroll
    for (int t = 0; t < 8; t++) {
        sk += g_partK[t * (NB * DIM) + idx];
        sq += g_partQ[t * (NB * DIM) + idx];
    }
    g_DK2[idx] = sk;
    g_DQ2[idx] = sq;
}

// Row softmax of YT -> SM (scaled x128) fp16
__global__ __launch_bounds__(256)
void softmax_k()
{
    const int row = blockIdx.x;
    const int tid = threadIdx.x;
    float* y = g_YT + ((size_t)row << 10);
    float v[4];
    #pragma unroll
    for (int j = 0; j < 4; j++) v[j] = y[tid + j * 256];
    float m = fmaxf(fmaxf(v[0], v[1]), fmaxf(v[2], v[3]));
    __shared__ float red[8];
    #pragma unroll
    for (int o = 16; o > 0; o >>= 1) m = fmaxf(m, __shfl_xor_sync(0xFFFFFFFFu, m, o));
    if ((tid & 31) == 0) red[tid >> 5] = m;
    __syncthreads();
    float mall = red[0];
    #pragma unroll
    for (int w = 1; w < 8; w++) mall = fmaxf(mall, red[w]);
    float s = 0.f;
    #pragma unroll
    for (int j = 0; j < 4; j++) { v[j] = __expf(v[j] - mall); s += v[j]; }
    #pragma unroll
    for (int o = 16; o > 0; o >>= 1) s += __shfl_xor_sync(0xFFFFFFFFu, s, o);
    __syncthreads();
    if ((tid & 31) == 0) red[tid >> 5] = s;
    __syncthreads();
    float st = 0.f;
    #pragma unroll
    for (int w = 0; w < 8; w++) st += red[w];
    const float inv = SM_SCALE / st;
    #pragma unroll
    for (int j = 0; j < 4; j++)
        g_SM_h[((size_t)row << 10) + tid + j * 256] = __float2half(v[j] * inv);
}

// ---------------------------------------------------------------------------
extern "C" void kernel_launch(void* const* d_in, const int* in_sizes, int n_in,
                              void* d_out, int out_size)
{
    const float* X   = (const float*)d_in[0];
    const float* Wk  = (const float*)d_in[1];
    const float* Wq  = (const float*)d_in[2];
    const float* Wk0 = (const float*)d_in[3];
    const float* Wq0 = (const float*)d_in[4];
    float* Z = (float*)d_out;

    cudaFuncSetAttribute(mma_gemm<0>, cudaFuncAttributeMaxDynamicSharedMemorySize, SMEM_BYTES);
    cudaFuncSetAttribute(mma_gemm<1>, cudaFuncAttributeMaxDynamicSharedMemorySize, SMEM_BYTES);
    cudaFuncSetAttribute(mma_gemm<2>, cudaFuncAttributeMaxDynamicSharedMemorySize, SMEM_BYTES);

    __half *Wkh, *Wqh, *Xh, *XTh, *KTh, *QTh, *SMh;
    float *YT, *dk2, *dq2, *pK, *pQ;
    cudaGetSymbolAddress((void**)&Wkh, g_Wk_h);   cudaGetSymbolAddress((void**)&Wqh, g_Wq_h);
    cudaGetSymbolAddress((void**)&Xh,  g_X_h);    cudaGetSymbolAddress((void**)&XTh, g_XT_h);
    cudaGetSymbolAddress((void**)&KTh, g_KT_h);   cudaGetSymbolAddress((void**)&QTh, g_QT_h);
    cudaGetSymbolAddress((void**)&SMh, g_SM_h);
    cudaGetSymbolAddress((void**)&YT,  g_YT);
    cudaGetSymbolAddress((void**)&dk2, g_DK2);    cudaGetSymbolAddress((void**)&dq2, g_DQ2);
    cudaGetSymbolAddress((void**)&pK,  g_partK);  cudaGetSymbolAddress((void**)&pQ,  g_partQ);

    const size_t S = (size_t)DIM * DIM;
    dim3 ggKQ(8, 8, 2 * NB);
    dim3 gg(8, 8, NB);

    w_split<<<(DIM * DIM) / 256, 256>>>(Wk, Wq);
    xprep<<<dim3(32, 32, NB), dim3(32, 8)>>>(X);

    // Merged: KT = (Wk @ X)^T + Wk0, QT = (Wq @ X)^T + Wq0; fused exact norms
    mma_gemm<0><<<ggKQ, 256, SMEM_BYTES>>>(Wkh, Wqh, 0, XTh, S,
                                           nullptr, KTh, QTh, Wk0, Wq0,
                                           nullptr, nullptr, pK, pQ, 1.0f);
    norms_red<<<(NB * DIM) / 256, 256>>>();

    // YT[k,q] = (Q^T K)[q,k] * rsqrt(max(DQ2[q]*DK2[k], eps)), direct stores
    mma_gemm<1><<<gg, 256, SMEM_BYTES>>>(QTh, nullptr, S, KTh, S,
                                         YT, nullptr, nullptr, nullptr, nullptr,
                                         dq2, dk2, nullptr, nullptr, 1.0f);
    softmax_k<<<NB * DIM, 256>>>();

    // Z = X @ (SM*128) / 128, direct float2 stores
    mma_gemm<2><<<gg, 256, SMEM_BYTES>>>(Xh, nullptr, S, SMh, S,
                                         Z, nullptr, nullptr, nullptr, nullptr,
                                         nullptr, nullptr, nullptr, nullptr,
                                         SM_DESCALE);
}